// round 1
// baseline (speedup 1.0000x reference)
#include <cuda_runtime.h>

// Problem constants
#define B_DIM   64
#define N_DIM   10000
#define C0      128
#define C1      64
#define C2      256
#define M_TOTAL (B_DIM * N_DIM)   // 640000

// GEMM tiling
#define BM 128
#define BN 128
#define BK 16
#define TM 8
#define TN 8
#define AS_PITCH 132   // 128 + 4 pad: breaks STS bank conflicts, keeps float4 align

// Constant bias: be[c] + sum_j k0[j] * We[128+j, c], where k0 = MLP(0)
__device__ float d_cbias[C2];

__global__ void cbias_kernel(const float* __restrict__ b1,
                             const float* __restrict__ W2, const float* __restrict__ b2,
                             const float* __restrict__ W3, const float* __restrict__ b3,
                             const float* __restrict__ We, const float* __restrict__ be) {
    __shared__ float h2s[16];
    __shared__ float k0s[64];
    const int t = threadIdx.x;

    // h1 = relu(0 @ W1 + b1) = relu(b1); h2 = relu(h1 @ W2 + b2)
    if (t < 16) {
        float acc = b2[t];
        #pragma unroll
        for (int i = 0; i < 8; ++i) {
            float h1 = fmaxf(b1[i], 0.0f);
            acc = fmaf(h1, W2[i * 16 + t], acc);
        }
        h2s[t] = fmaxf(acc, 0.0f);
    }
    __syncthreads();

    // k0 = h2 @ W3 + b3
    if (t < 64) {
        float acc = b3[t];
        #pragma unroll
        for (int j = 0; j < 16; ++j)
            acc = fmaf(h2s[j], W3[j * 64 + t], acc);
        k0s[t] = acc;
    }
    __syncthreads();

    // cbias[c] = be[c] + sum_{j<64} k0[j] * We[(128+j)*256 + c]
    float acc = be[t];
    #pragma unroll 8
    for (int j = 0; j < 64; ++j)
        acc = fmaf(k0s[j], We[(C0 + j) * C2 + t], acc);
    d_cbias[t] = acc;
}

// out[(n*64 + b)*256 + c] = sum_k feature[(b*10000 + n)*128 + k] * We[k*256 + c] + cbias[c]
__global__ __launch_bounds__(256)
void patch_encoder_gemm(const float* __restrict__ A,    // feature, [M_TOTAL, 128] row-major
                        const float* __restrict__ We,   // [192, 256]; rows 0..127 used here
                        float* __restrict__ out) {
    __shared__ float As[2][BK][AS_PITCH];  // transposed: As[k][m]
    __shared__ float Bs[2][BK][BN];        // Bs[k][n]

    const int tid = threadIdx.x;
    const int tx  = tid & 15;    // 0..15 -> n microtile
    const int ty  = tid >> 4;    // 0..15 -> m microtile
    const int mBase = blockIdx.x * BM;
    const int nBase = blockIdx.y * BN;

    // Loader mapping (256 threads, 2 float4 each per tile)
    const int aRow  = tid >> 2;   // 0..63, +64 for second chunk
    const int aColV = tid & 3;    // float4 index within BK=16
    const int bKr   = tid >> 5;   // 0..7, +8 for second chunk
    const int bColV = tid & 31;   // float4 index within BN=128

    float acc[TM][TN];
    #pragma unroll
    for (int i = 0; i < TM; ++i)
        #pragma unroll
        for (int j = 0; j < TN; ++j)
            acc[i][j] = 0.0f;

    auto load_tiles = [&](int kt, int buf) {
        #pragma unroll
        for (int r = 0; r < 2; ++r) {
            const int row = aRow + r * 64;
            float4 v = *(const float4*)(A + (size_t)(mBase + row) * C0 + kt * BK + aColV * 4);
            As[buf][aColV * 4 + 0][row] = v.x;
            As[buf][aColV * 4 + 1][row] = v.y;
            As[buf][aColV * 4 + 2][row] = v.z;
            As[buf][aColV * 4 + 3][row] = v.w;
        }
        #pragma unroll
        for (int r = 0; r < 2; ++r) {
            const int kr = bKr + r * 8;
            float4 v = *(const float4*)(We + (size_t)(kt * BK + kr) * C2 + nBase + bColV * 4);
            *(float4*)&Bs[buf][kr][bColV * 4] = v;
        }
    };

    load_tiles(0, 0);
    __syncthreads();

    int buf = 0;
    #pragma unroll 1
    for (int kt = 0; kt < C0 / BK; ++kt) {
        if (kt + 1 < C0 / BK)
            load_tiles(kt + 1, buf ^ 1);   // global -> other smem buffer, overlaps compute

        #pragma unroll
        for (int k = 0; k < BK; ++k) {
            float a[TM], b[TN];
            *(float4*)&a[0] = *(const float4*)&As[buf][k][ty * TM];
            *(float4*)&a[4] = *(const float4*)&As[buf][k][ty * TM + 4];
            *(float4*)&b[0] = *(const float4*)&Bs[buf][k][tx * TN];
            *(float4*)&b[4] = *(const float4*)&Bs[buf][k][tx * TN + 4];
            #pragma unroll
            for (int i = 0; i < TM; ++i)
                #pragma unroll
                for (int j = 0; j < TN; ++j)
                    acc[i][j] = fmaf(a[i], b[j], acc[i][j]);
        }
        __syncthreads();
        buf ^= 1;
    }

    // Epilogue: add cbias, store to transposed output layout [n, b, c]
    float cb[TN];
    *(float4*)&cb[0] = *(const float4*)&d_cbias[nBase + tx * TN];
    *(float4*)&cb[4] = *(const float4*)&d_cbias[nBase + tx * TN + 4];

    const int rBase = mBase + ty * TM;
    #pragma unroll
    for (int i = 0; i < TM; ++i) {
        const int r  = rBase + i;
        const int bb = r / N_DIM;            // batch index
        const int nn = r - bb * N_DIM;       // node index
        float* o = out + ((size_t)nn * B_DIM + bb) * C2 + nBase + tx * TN;
        float4 v0, v1;
        v0.x = acc[i][0] + cb[0];
        v0.y = acc[i][1] + cb[1];
        v0.z = acc[i][2] + cb[2];
        v0.w = acc[i][3] + cb[3];
        v1.x = acc[i][4] + cb[4];
        v1.y = acc[i][5] + cb[5];
        v1.z = acc[i][6] + cb[6];
        v1.w = acc[i][7] + cb[7];
        *(float4*)(o + 0) = v0;
        *(float4*)(o + 4) = v1;
    }
}

extern "C" void kernel_launch(void* const* d_in, const int* in_sizes, int n_in,
                              void* d_out, int out_size) {
    const float* feature = (const float*)d_in[0];
    // d_in[1] = coordinates (unused: kernel row is always MLP(0))
    // d_in[2] = W1 (unused: input to layer 1 is the zero vector)
    const float* b1 = (const float*)d_in[3];
    const float* W2 = (const float*)d_in[4];
    const float* b2 = (const float*)d_in[5];
    const float* W3 = (const float*)d_in[6];
    const float* b3 = (const float*)d_in[7];
    const float* We = (const float*)d_in[8];
    const float* be = (const float*)d_in[9];
    float* out = (float*)d_out;

    cbias_kernel<<<1, C2>>>(b1, W2, b2, W3, b3, We, be);

    dim3 grid(M_TOTAL / BM, C2 / BN);   // (5000, 2), exact — no bounds checks
    patch_encoder_gemm<<<grid, 256>>>(feature, We, out);
}

// round 4
// speedup vs baseline: 2.5832x; 2.5832x over previous
#include <cuda_runtime.h>
#include <cstdint>

// Problem constants
#define B_DIM   64
#define N_DIM   10000
#define C0      128
#define C1      64
#define C2      256
#define M_TOTAL (B_DIM * N_DIM)   // 640000

// GEMM tiling
#define BM 128
#define BN 256
#define BK 32
#define NKCHUNK (C0 / BK)         // 4
#define NTHREADS 256              // 8 warps: 2 (M) x 4 (N), warp tile 64x64

// smem pitch in floats: 36 -> bank = (4*row + col) % 32, conflict-free fragments
#define PITCH 36
#define SMEM_FLOATS ((BM + BN) * PITCH * 2)            // double-buffered
#define SMEM_BYTES  (SMEM_FLOATS * 4)                  // 110592

// Precomputed: Bt[n][k] = rna_tf32(We[k][n]) for k<128; cbias[c]
__device__ float d_Bt[BN * C0];
__device__ float d_cbias[C2];

// ---------------- helpers ----------------
__device__ __forceinline__ uint32_t smem_u32(const void* p) {
    uint32_t a;
    asm("{ .reg .u64 t; cvta.to.shared.u64 t, %1; cvt.u32.u64 %0, t; }" : "=r"(a) : "l"(p));
    return a;
}

__device__ __forceinline__ uint32_t f2tf32(float f) {
    uint32_t u;
    asm("cvt.rna.tf32.f32 %0, %1;" : "=r"(u) : "f"(f));
    return u;
}

__device__ __forceinline__ void cp_async16(uint32_t saddr, const void* gaddr) {
    asm volatile("cp.async.cg.shared.global [%0], [%1], 16;" :: "r"(saddr), "l"(gaddr));
}
#define CP_COMMIT() asm volatile("cp.async.commit_group;")
#define CP_WAIT(n)  asm volatile("cp.async.wait_group %0;" :: "n"(n))

__device__ __forceinline__ void mma_tf32(float* c, const uint32_t* a, const uint32_t* b) {
    asm volatile(
        "mma.sync.aligned.m16n8k8.row.col.f32.tf32.tf32.f32 "
        "{%0,%1,%2,%3}, {%4,%5,%6,%7}, {%8,%9}, {%0,%1,%2,%3};"
        : "+f"(c[0]), "+f"(c[1]), "+f"(c[2]), "+f"(c[3])
        : "r"(a[0]), "r"(a[1]), "r"(a[2]), "r"(a[3]), "r"(b[0]), "r"(b[1]));
}

// ---------------- prologue: Bt + cbias ----------------
__global__ void prep_kernel(const float* __restrict__ b1,
                            const float* __restrict__ W2, const float* __restrict__ b2,
                            const float* __restrict__ W3, const float* __restrict__ b3,
                            const float* __restrict__ We, const float* __restrict__ be) {
    __shared__ float h2s[16];
    __shared__ float k0s[64];
    const int t = threadIdx.x;

    // Bt[n][k] = rna(We[k*256 + n]); thread t owns column n=t, reads coalesced per k
    #pragma unroll 4
    for (int k = 0; k < C0; ++k)
        d_Bt[t * C0 + k] = __uint_as_float(f2tf32(We[(size_t)k * C2 + t]));

    // cbias: MLP(0) folded through encoder
    if (t < 16) {
        float acc = b2[t];
        #pragma unroll
        for (int i = 0; i < 8; ++i)
            acc = fmaf(fmaxf(b1[i], 0.0f), W2[i * 16 + t], acc);
        h2s[t] = fmaxf(acc, 0.0f);
    }
    __syncthreads();
    if (t < 64) {
        float acc = b3[t];
        #pragma unroll
        for (int j = 0; j < 16; ++j)
            acc = fmaf(h2s[j], W3[j * 64 + t], acc);
        k0s[t] = acc;
    }
    __syncthreads();
    float acc = be[t];
    #pragma unroll 8
    for (int j = 0; j < 64; ++j)
        acc = fmaf(k0s[j], We[(C0 + j) * C2 + t], acc);
    d_cbias[t] = acc;
}

// ---------------- main GEMM: tf32 mma.sync ----------------
__global__ __launch_bounds__(NTHREADS, 1)
void patch_encoder_mma(const float* __restrict__ A,  // feature [640000, 128]
                       float* __restrict__ out) {
    extern __shared__ float smem[];
    float* As = smem;                       // [2][BM][PITCH]
    float* Bs = smem + 2 * BM * PITCH;      // [2][BN][PITCH]

    const int tid  = (int)threadIdx.x;
    const int wid  = tid >> 5;
    const int lane = tid & 31;
    const int gid  = lane >> 2;     // 0..7
    const int tig  = lane & 3;      // 0..3
    const int warpM = wid >> 2;     // 0..1
    const int warpN = wid & 3;      // 0..3
    const int mBase = (int)blockIdx.x * BM;

    const uint32_t sA = smem_u32(As);
    const uint32_t sB = smem_u32(Bs);

    float acc[4][8][4];
    #pragma unroll
    for (int mt = 0; mt < 4; ++mt)
        #pragma unroll
        for (int nt = 0; nt < 8; ++nt)
            #pragma unroll
            for (int q = 0; q < 4; ++q)
                acc[mt][nt][q] = 0.0f;

    // cp.async loaders: A chunk = 128 rows x 128B (1024 x 16B), B chunk = 256 x 128B (2048 x 16B)
    auto load_chunk = [&](int c, int buf) {
        const int kf = c * BK;   // float offset in K
        #pragma unroll
        for (int i = 0; i < 4; ++i) {
            const int e = tid + i * NTHREADS;        // 16B unit
            const int row = e >> 3, col = e & 7;     // col: 16B units within 128B
            uint32_t dst = sA + ((buf * BM + row) * PITCH + col * 4) * 4;
            cp_async16(dst, A + (size_t)(mBase + row) * C0 + kf + col * 4);
        }
        #pragma unroll
        for (int i = 0; i < 8; ++i) {
            const int e = tid + i * NTHREADS;
            const int row = e >> 3, col = e & 7;
            uint32_t dst = sB + ((buf * BN + row) * PITCH + col * 4) * 4;
            cp_async16(dst, d_Bt + (size_t)row * C0 + kf + col * 4);
        }
        CP_COMMIT();
    };

    load_chunk(0, 0);

    #pragma unroll
    for (int c = 0; c < NKCHUNK; ++c) {
        const int buf = c & 1;
        if (c + 1 < NKCHUNK) {
            load_chunk(c + 1, buf ^ 1);
            CP_WAIT(1);
        } else {
            CP_WAIT(0);
        }
        __syncthreads();

        const float* Ab = As + (buf * BM) * PITCH;
        const float* Bb = Bs + (buf * BN) * PITCH;

        #pragma unroll
        for (int k8 = 0; k8 < BK / 8; ++k8) {
            const int kb = k8 * 8;
            uint32_t a[4][4];
            #pragma unroll
            for (int mt = 0; mt < 4; ++mt) {
                const int r0 = warpM * 64 + mt * 16 + gid;
                a[mt][0] = f2tf32(Ab[(r0)     * PITCH + kb + tig]);
                a[mt][1] = f2tf32(Ab[(r0 + 8) * PITCH + kb + tig]);
                a[mt][2] = f2tf32(Ab[(r0)     * PITCH + kb + tig + 4]);
                a[mt][3] = f2tf32(Ab[(r0 + 8) * PITCH + kb + tig + 4]);
            }
            uint32_t b[8][2];
            #pragma unroll
            for (int nt = 0; nt < 8; ++nt) {
                const int n = warpN * 64 + nt * 8 + gid;
                b[nt][0] = __float_as_uint(Bb[n * PITCH + kb + tig]);
                b[nt][1] = __float_as_uint(Bb[n * PITCH + kb + tig + 4]);
            }
            #pragma unroll
            for (int mt = 0; mt < 4; ++mt)
                #pragma unroll
                for (int nt = 0; nt < 8; ++nt)
                    mma_tf32(acc[mt][nt], a[mt], b[nt]);
        }
        __syncthreads();   // all warps done with buf before it is refilled
    }

    // ---- epilogue: + cbias, transposed store out[(nn*64+bb)*256 + c] ----
    #pragma unroll
    for (int mt = 0; mt < 4; ++mt) {
        const int r0 = mBase + warpM * 64 + mt * 16 + gid;
        const int r1 = r0 + 8;
        const int bb0 = r0 / N_DIM, nn0 = r0 - bb0 * N_DIM;
        const int bb1 = r1 / N_DIM, nn1 = r1 - bb1 * N_DIM;
        float* o0 = out + ((size_t)nn0 * B_DIM + bb0) * C2;
        float* o1 = out + ((size_t)nn1 * B_DIM + bb1) * C2;
        #pragma unroll
        for (int nt = 0; nt < 8; ++nt) {
            const int ncol = warpN * 64 + nt * 8 + 2 * tig;
            const float2 cb = *(const float2*)&d_cbias[ncol];
            float2 v0, v1;
            v0.x = acc[mt][nt][0] + cb.x;
            v0.y = acc[mt][nt][1] + cb.y;
            v1.x = acc[mt][nt][2] + cb.x;
            v1.y = acc[mt][nt][3] + cb.y;
            *(float2*)(o0 + ncol) = v0;
            *(float2*)(o1 + ncol) = v1;
        }
    }
}

extern "C" void kernel_launch(void* const* d_in, const int* in_sizes, int n_in,
                              void* d_out, int out_size) {
    const float* feature = (const float*)d_in[0];
    const float* b1 = (const float*)d_in[3];
    const float* W2 = (const float*)d_in[4];
    const float* b2 = (const float*)d_in[5];
    const float* W3 = (const float*)d_in[6];
    const float* b3 = (const float*)d_in[7];
    const float* We = (const float*)d_in[8];
    const float* be = (const float*)d_in[9];
    float* out = (float*)d_out;

    cudaFuncSetAttribute(patch_encoder_mma,
                         cudaFuncAttributeMaxDynamicSharedMemorySize, SMEM_BYTES);

    prep_kernel<<<1, C2>>>(b1, W2, b2, W3, b3, We, be);
    patch_encoder_mma<<<M_TOTAL / BM, NTHREADS, SMEM_BYTES>>>(feature, out);
}

// round 6
// speedup vs baseline: 2.5903x; 1.0027x over previous
#include <cuda_runtime.h>
#include <cstdint>

// Problem constants
#define B_DIM   64
#define N_DIM   10000
#define C0      128
#define C1      64
#define C2      256
#define M_TOTAL (B_DIM * N_DIM)   // 640000

// GEMM tiling
#define BM 128
#define BN 256
#define BK 32
#define NKCHUNK (C0 / BK)         // 4 chunks; ALL resident in smem (no refill)
#define NTHREADS 512              // 16 warps: 2 (M) x 8 (N), warp tile 64x32

// smem pitch in floats: 36 -> bank = (4*row + col) % 32, conflict-free fragments
#define PITCH 36
#define CHUNK_FLOATS ((BM + BN) * PITCH)
#define SMEM_BYTES (CHUNK_FLOATS * NKCHUNK * 4)   // 221184 B: full K resident

// Precomputed: Bt[n][k] = rna_tf32(We[k][n]) for k<128; cbias[c]
__device__ float d_Bt[BN * C0];
__device__ float d_cbias[C2];

// ---------------- helpers ----------------
__device__ __forceinline__ uint32_t smem_u32(const void* p) {
    uint32_t a;
    asm("{ .reg .u64 t; cvta.to.shared.u64 t, %1; cvt.u32.u64 %0, t; }" : "=r"(a) : "l"(p));
    return a;
}

__device__ __forceinline__ uint32_t f2tf32(float f) {
    uint32_t u;
    asm("cvt.rna.tf32.f32 %0, %1;" : "=r"(u) : "f"(f));
    return u;
}

__device__ __forceinline__ void cp_async16(uint32_t saddr, const void* gaddr) {
    asm volatile("cp.async.cg.shared.global [%0], [%1], 16;" :: "r"(saddr), "l"(gaddr));
}
#define CP_COMMIT() asm volatile("cp.async.commit_group;")
#define CP_WAIT(n)  asm volatile("cp.async.wait_group %0;" :: "n"(n))

__device__ __forceinline__ void mma_tf32(float* c, const uint32_t* a, const uint32_t* b) {
    asm volatile(
        "mma.sync.aligned.m16n8k8.row.col.f32.tf32.tf32.f32 "
        "{%0,%1,%2,%3}, {%4,%5,%6,%7}, {%8,%9}, {%0,%1,%2,%3};"
        : "+f"(c[0]), "+f"(c[1]), "+f"(c[2]), "+f"(c[3])
        : "r"(a[0]), "r"(a[1]), "r"(a[2]), "r"(a[3]), "r"(b[0]), "r"(b[1]));
}

// ---------------- prologue: Bt + cbias ----------------
__global__ void prep_kernel(const float* __restrict__ b1,
                            const float* __restrict__ W2, const float* __restrict__ b2,
                            const float* __restrict__ W3, const float* __restrict__ b3,
                            const float* __restrict__ We, const float* __restrict__ be) {
    __shared__ float h2s[16];
    __shared__ float k0s[64];
    const int t = threadIdx.x;

    // Bt[n][k] = rna(We[k*256 + n]); thread t owns column n=t, reads coalesced per k
    #pragma unroll 4
    for (int k = 0; k < C0; ++k)
        d_Bt[t * C0 + k] = __uint_as_float(f2tf32(We[(size_t)k * C2 + t]));

    // cbias: MLP(0) folded through encoder
    if (t < 16) {
        float acc = b2[t];
        #pragma unroll
        for (int i = 0; i < 8; ++i)
            acc = fmaf(fmaxf(b1[i], 0.0f), W2[i * 16 + t], acc);
        h2s[t] = fmaxf(acc, 0.0f);
    }
    __syncthreads();
    if (t < 64) {
        float acc = b3[t];
        #pragma unroll
        for (int j = 0; j < 16; ++j)
            acc = fmaf(h2s[j], W3[j * 64 + t], acc);
        k0s[t] = acc;
    }
    __syncthreads();
    float acc = be[t];
    #pragma unroll 8
    for (int j = 0; j < 64; ++j)
        acc = fmaf(k0s[j], We[(C0 + j) * C2 + t], acc);
    d_cbias[t] = acc;
}

// ---------------- main GEMM: tf32 mma.sync, full-K-resident pipeline ----------------
__global__ __launch_bounds__(NTHREADS, 1)
void patch_encoder_mma(const float* __restrict__ A,  // feature [640000, 128]
                       float* __restrict__ out) {
    extern __shared__ float smem[];   // [NKCHUNK] x { A[BM][PITCH], B[BN][PITCH] }

    const int tid  = (int)threadIdx.x;
    const int wid  = tid >> 5;
    const int lane = tid & 31;
    const int gid  = lane >> 2;     // 0..7
    const int tig  = lane & 3;      // 0..3
    const int warpM = wid >> 3;     // 0..1
    const int warpN = wid & 7;      // 0..7
    const int mBase = (int)blockIdx.x * BM;

    const uint32_t sbase = smem_u32(smem);

    float acc[4][4][4];
    #pragma unroll
    for (int mt = 0; mt < 4; ++mt)
        #pragma unroll
        for (int nt = 0; nt < 4; ++nt)
            #pragma unroll
            for (int q = 0; q < 4; ++q)
                acc[mt][nt][q] = 0.0f;

    // Front-load ALL K chunks: one commit group per chunk.
    // A chunk = 1024 x 16B units, B chunk = 2048 x 16B units, 512 threads.
    #pragma unroll
    for (int c = 0; c < NKCHUNK; ++c) {
        const int kf = c * BK;
        const uint32_t sA = sbase + (c * CHUNK_FLOATS) * 4;
        const uint32_t sB = sA + BM * PITCH * 4;
        #pragma unroll
        for (int i = 0; i < 2; ++i) {
            const int e = tid + i * NTHREADS;
            const int row = e >> 3, col = e & 7;
            cp_async16(sA + (row * PITCH + col * 4) * 4,
                       A + (size_t)(mBase + row) * C0 + kf + col * 4);
        }
        #pragma unroll
        for (int i = 0; i < 4; ++i) {
            const int e = tid + i * NTHREADS;
            const int row = e >> 3, col = e & 7;
            cp_async16(sB + (row * PITCH + col * 4) * 4,
                       d_Bt + (size_t)row * C0 + kf + col * 4);
        }
        CP_COMMIT();
    }

    #pragma unroll
    for (int c = 0; c < NKCHUNK; ++c) {
        // wait until chunk c (and everything before it) has landed
        if (c == 0)      CP_WAIT(3);
        else if (c == 1) CP_WAIT(2);
        else if (c == 2) CP_WAIT(1);
        else             CP_WAIT(0);
        __syncthreads();

        const float* Ab = smem + c * CHUNK_FLOATS;
        const float* Bb = Ab + BM * PITCH;

        #pragma unroll
        for (int k8 = 0; k8 < BK / 8; ++k8) {
            const int kb = k8 * 8;
            uint32_t a[4][4];
            #pragma unroll
            for (int mt = 0; mt < 4; ++mt) {
                const int r0 = warpM * 64 + mt * 16 + gid;
                a[mt][0] = f2tf32(Ab[(r0)     * PITCH + kb + tig]);
                a[mt][1] = f2tf32(Ab[(r0 + 8) * PITCH + kb + tig]);
                a[mt][2] = f2tf32(Ab[(r0)     * PITCH + kb + tig + 4]);
                a[mt][3] = f2tf32(Ab[(r0 + 8) * PITCH + kb + tig + 4]);
            }
            uint32_t b[4][2];
            #pragma unroll
            for (int nt = 0; nt < 4; ++nt) {
                const int n = warpN * 32 + nt * 8 + gid;
                b[nt][0] = __float_as_uint(Bb[n * PITCH + kb + tig]);
                b[nt][1] = __float_as_uint(Bb[n * PITCH + kb + tig + 4]);
            }
            #pragma unroll
            for (int mt = 0; mt < 4; ++mt)
                #pragma unroll
                for (int nt = 0; nt < 4; ++nt)
                    mma_tf32(acc[mt][nt], a[mt], b[nt]);
        }
        // no trailing sync: buffers are never rewritten
    }

    // ---- epilogue: + cbias, transposed store out[(nn*64+bb)*256 + c] ----
    #pragma unroll
    for (int mt = 0; mt < 4; ++mt) {
        const int r0 = mBase + warpM * 64 + mt * 16 + gid;
        const int r1 = r0 + 8;
        const int bb0 = r0 / N_DIM, nn0 = r0 - bb0 * N_DIM;
        const int bb1 = r1 / N_DIM, nn1 = r1 - bb1 * N_DIM;
        float* o0 = out + ((size_t)nn0 * B_DIM + bb0) * C2;
        float* o1 = out + ((size_t)nn1 * B_DIM + bb1) * C2;
        #pragma unroll
        for (int nt = 0; nt < 4; ++nt) {
            const int ncol = warpN * 32 + nt * 8 + 2 * tig;
            const float2 cb = *(const float2*)&d_cbias[ncol];
            float2 v0, v1;
            v0.x = acc[mt][nt][0] + cb.x;
            v0.y = acc[mt][nt][1] + cb.y;
            v1.x = acc[mt][nt][2] + cb.x;
            v1.y = acc[mt][nt][3] + cb.y;
            *(float2*)(o0 + ncol) = v0;
            *(float2*)(o1 + ncol) = v1;
        }
    }
}

extern "C" void kernel_launch(void* const* d_in, const int* in_sizes, int n_in,
                              void* d_out, int out_size) {
    const float* feature = (const float*)d_in[0];
    const float* b1 = (const float*)d_in[3];
    const float* W2 = (const float*)d_in[4];
    const float* b2 = (const float*)d_in[5];
    const float* W3 = (const float*)d_in[6];
    const float* b3 = (const float*)d_in[7];
    const float* We = (const float*)d_in[8];
    const float* be = (const float*)d_in[9];
    float* out = (float*)d_out;

    cudaFuncSetAttribute(patch_encoder_mma,
                         cudaFuncAttributeMaxDynamicSharedMemorySize, SMEM_BYTES);

    prep_kernel<<<1, C2>>>(b1, W2, b2, W3, b3, We, be);
    patch_encoder_mma<<<M_TOTAL / BM, NTHREADS, SMEM_BYTES>>>(feature, out);
}

// round 7
// speedup vs baseline: 2.6760x; 1.0331x over previous
#include <cuda_runtime.h>
#include <cstdint>

// Problem constants
#define B_DIM   64
#define N_DIM   10000
#define C0      128
#define C1      64
#define C2      256
#define M_TOTAL (B_DIM * N_DIM)   // 640000

// GEMM tiling: CTA tile 64 x 256 (full C2) so A is read exactly once.
#define BM 64
#define BN 256
#define BK 32
#define NKCHUNK (C0 / BK)         // 4
#define NTHREADS 256              // 8 warps: 2 (M) x 4 (N), warp tile 32x64

// smem pitch in floats: 36 -> bank = (4*row + col) % 32, conflict-free fragments
#define PITCH 36
#define CHUNK_FLOATS ((BM + BN) * PITCH)
#define SMEM_BYTES (CHUNK_FLOATS * 2 * 4)   // double-buffered: 92160 B -> 2 CTAs/SM

// Precomputed: Bt[n][k] = rna_tf32(We[k][n]) for k<128; cbias[c]
__device__ float d_Bt[BN * C0];
__device__ float d_cbias[C2];

// ---------------- helpers ----------------
__device__ __forceinline__ uint32_t smem_u32(const void* p) {
    uint32_t a;
    asm("{ .reg .u64 t; cvta.to.shared.u64 t, %1; cvt.u32.u64 %0, t; }" : "=r"(a) : "l"(p));
    return a;
}

__device__ __forceinline__ uint32_t f2tf32(float f) {
    uint32_t u;
    asm("cvt.rna.tf32.f32 %0, %1;" : "=r"(u) : "f"(f));
    return u;
}

__device__ __forceinline__ void cp_async16(uint32_t saddr, const void* gaddr) {
    asm volatile("cp.async.cg.shared.global [%0], [%1], 16;" :: "r"(saddr), "l"(gaddr));
}
#define CP_COMMIT() asm volatile("cp.async.commit_group;")
#define CP_WAIT(n)  asm volatile("cp.async.wait_group %0;" :: "n"(n))

__device__ __forceinline__ void mma_tf32(float* c, const uint32_t* a, const uint32_t* b) {
    asm volatile(
        "mma.sync.aligned.m16n8k8.row.col.f32.tf32.tf32.f32 "
        "{%0,%1,%2,%3}, {%4,%5,%6,%7}, {%8,%9}, {%0,%1,%2,%3};"
        : "+f"(c[0]), "+f"(c[1]), "+f"(c[2]), "+f"(c[3])
        : "r"(a[0]), "r"(a[1]), "r"(a[2]), "r"(a[3]), "r"(b[0]), "r"(b[1]));
}

// ---------------- prologue: Bt + cbias ----------------
__global__ void prep_kernel(const float* __restrict__ b1,
                            const float* __restrict__ W2, const float* __restrict__ b2,
                            const float* __restrict__ W3, const float* __restrict__ b3,
                            const float* __restrict__ We, const float* __restrict__ be) {
    __shared__ float h2s[16];
    __shared__ float k0s[64];
    const int t = threadIdx.x;

    // Bt[n][k] = rna(We[k*256 + n]); thread t owns column n=t, reads coalesced per k
    #pragma unroll 4
    for (int k = 0; k < C0; ++k)
        d_Bt[t * C0 + k] = __uint_as_float(f2tf32(We[(size_t)k * C2 + t]));

    // cbias: MLP(0) folded through encoder
    if (t < 16) {
        float acc = b2[t];
        #pragma unroll
        for (int i = 0; i < 8; ++i)
            acc = fmaf(fmaxf(b1[i], 0.0f), W2[i * 16 + t], acc);
        h2s[t] = fmaxf(acc, 0.0f);
    }
    __syncthreads();
    if (t < 64) {
        float acc = b3[t];
        #pragma unroll
        for (int j = 0; j < 16; ++j)
            acc = fmaf(h2s[j], W3[j * 64 + t], acc);
        k0s[t] = acc;
    }
    __syncthreads();
    float acc = be[t];
    #pragma unroll 8
    for (int j = 0; j < 64; ++j)
        acc = fmaf(k0s[j], We[(C0 + j) * C2 + t], acc);
    d_cbias[t] = acc;
}

// ---------------- main GEMM: tf32 mma.sync, 2 CTAs/SM for phase overlap ----------------
__global__ __launch_bounds__(NTHREADS, 2)
void patch_encoder_mma(const float* __restrict__ A,  // feature [640000, 128]
                       float* __restrict__ out) {
    extern __shared__ float smem[];   // [2 bufs] x { A[BM][PITCH], B[BN][PITCH] }

    const int tid  = (int)threadIdx.x;
    const int wid  = tid >> 5;
    const int lane = tid & 31;
    const int gid  = lane >> 2;     // 0..7
    const int tig  = lane & 3;      // 0..3
    const int warpM = wid >> 2;     // 0..1 -> 32-row slice
    const int warpN = wid & 3;      // 0..3 -> 64-col slice
    const int mBase = (int)blockIdx.x * BM;

    const uint32_t sbase = smem_u32(smem);

    float acc[2][8][4];
    #pragma unroll
    for (int mt = 0; mt < 2; ++mt)
        #pragma unroll
        for (int nt = 0; nt < 8; ++nt)
            #pragma unroll
            for (int q = 0; q < 4; ++q)
                acc[mt][nt][q] = 0.0f;

    // Loader: A chunk = 64 rows x 8 (16B units) = 512; B chunk = 256 x 8 = 2048. 256 threads.
    auto load_chunk = [&](int c, int buf) {
        const int kf = c * BK;
        const uint32_t sA = sbase + (buf * CHUNK_FLOATS) * 4;
        const uint32_t sB = sA + BM * PITCH * 4;
        #pragma unroll
        for (int i = 0; i < 2; ++i) {
            const int e = tid + i * NTHREADS;
            const int row = e >> 3, col = e & 7;
            cp_async16(sA + (row * PITCH + col * 4) * 4,
                       A + (size_t)(mBase + row) * C0 + kf + col * 4);
        }
        #pragma unroll
        for (int i = 0; i < 8; ++i) {
            const int e = tid + i * NTHREADS;
            const int row = e >> 3, col = e & 7;
            cp_async16(sB + (row * PITCH + col * 4) * 4,
                       d_Bt + (size_t)row * C0 + kf + col * 4);
        }
        CP_COMMIT();
    };

    load_chunk(0, 0);

    #pragma unroll
    for (int c = 0; c < NKCHUNK; ++c) {
        const int buf = c & 1;
        if (c + 1 < NKCHUNK) {
            load_chunk(c + 1, buf ^ 1);
            CP_WAIT(1);
        } else {
            CP_WAIT(0);
        }
        __syncthreads();

        const float* Ab = smem + buf * CHUNK_FLOATS;
        const float* Bb = Ab + BM * PITCH;

        #pragma unroll
        for (int k8 = 0; k8 < BK / 8; ++k8) {
            const int kb = k8 * 8;
            uint32_t a[2][4];
            #pragma unroll
            for (int mt = 0; mt < 2; ++mt) {
                const int r0 = warpM * 32 + mt * 16 + gid;
                a[mt][0] = f2tf32(Ab[(r0)     * PITCH + kb + tig]);
                a[mt][1] = f2tf32(Ab[(r0 + 8) * PITCH + kb + tig]);
                a[mt][2] = f2tf32(Ab[(r0)     * PITCH + kb + tig + 4]);
                a[mt][3] = f2tf32(Ab[(r0 + 8) * PITCH + kb + tig + 4]);
            }
            uint32_t b[8][2];
            #pragma unroll
            for (int nt = 0; nt < 8; ++nt) {
                const int n = warpN * 64 + nt * 8 + gid;
                b[nt][0] = __float_as_uint(Bb[n * PITCH + kb + tig]);
                b[nt][1] = __float_as_uint(Bb[n * PITCH + kb + tig + 4]);
            }
            #pragma unroll
            for (int mt = 0; mt < 2; ++mt)
                #pragma unroll
                for (int nt = 0; nt < 8; ++nt)
                    mma_tf32(acc[mt][nt], a[mt], b[nt]);
        }
        __syncthreads();
    }

    // ---- epilogue: + cbias, transposed store out[(nn*64+bb)*256 + c] ----
    #pragma unroll
    for (int mt = 0; mt < 2; ++mt) {
        const int r0 = mBase + warpM * 32 + mt * 16 + gid;
        const int r1 = r0 + 8;
        const int bb0 = r0 / N_DIM, nn0 = r0 - bb0 * N_DIM;
        const int bb1 = r1 / N_DIM, nn1 = r1 - bb1 * N_DIM;
        float* o0 = out + ((size_t)nn0 * B_DIM + bb0) * C2;
        float* o1 = out + ((size_t)nn1 * B_DIM + bb1) * C2;
        #pragma unroll
        for (int nt = 0; nt < 8; ++nt) {
            const int ncol = warpN * 64 + nt * 8 + 2 * tig;
            const float2 cb = *(const float2*)&d_cbias[ncol];
            float2 v0, v1;
            v0.x = acc[mt][nt][0] + cb.x;
            v0.y = acc[mt][nt][1] + cb.y;
            v1.x = acc[mt][nt][2] + cb.x;
            v1.y = acc[mt][nt][3] + cb.y;
            *(float2*)(o0 + ncol) = v0;
            *(float2*)(o1 + ncol) = v1;
        }
    }
}

extern "C" void kernel_launch(void* const* d_in, const int* in_sizes, int n_in,
                              void* d_out, int out_size) {
    const float* feature = (const float*)d_in[0];
    const float* b1 = (const float*)d_in[3];
    const float* W2 = (const float*)d_in[4];
    const float* b2 = (const float*)d_in[5];
    const float* W3 = (const float*)d_in[6];
    const float* b3 = (const float*)d_in[7];
    const float* We = (const float*)d_in[8];
    const float* be = (const float*)d_in[9];
    float* out = (float*)d_out;

    cudaFuncSetAttribute(patch_encoder_mma,
                         cudaFuncAttributeMaxDynamicSharedMemorySize, SMEM_BYTES);

    prep_kernel<<<1, C2>>>(b1, W2, b2, W3, b3, We, be);
    patch_encoder_mma<<<M_TOTAL / BM, NTHREADS, SMEM_BYTES>>>(feature, out);
}